// round 1
// baseline (speedup 1.0000x reference)
#include <cuda_runtime.h>
#include <cstdint>

// Problem constants
#define B    4
#define C    96
#define C3   288
#define HH   256
#define WW   256
#define HWPIX 65536           // 256*256
#define HEADS 3
#define HC   32
#define OUT_ELEMS (B * C * HWPIX)     // 25165824
#define ATTN_ELEMS (B * HEADS * HC * HC)

// ---------------- scratch (device globals; no runtime allocation) ----------------
__device__ float g_qkv[(size_t)B * C3 * HWPIX];  // post 1x1 conv   (~302 MB)
__device__ float g_dw [(size_t)B * C3 * HWPIX];  // post depthwise  (~302 MB); v = ch 192..287
__device__ float g_G  [B * HEADS * HC * HC];     // raw Gram q k^T
__device__ float g_qn [B * C];                   // sum q^2 per (b, qchannel)
__device__ float g_kn [B * C];
__device__ float g_M  [B * C * C];               // proj_w @ blockdiag(attn)

// ---------------- packed f32x2 helpers (Blackwell FFMA2 path) ----------------
typedef unsigned long long ull;

__device__ __forceinline__ ull pk2(float v) {
    ull r; asm("mov.b64 %0, {%1, %1};" : "=l"(r) : "f"(v)); return r;
}
__device__ __forceinline__ float2 unpk2(ull v) {
    float2 r; asm("mov.b64 {%0, %1}, %2;" : "=f"(r.x), "=f"(r.y) : "l"(v)); return r;
}
__device__ __forceinline__ ull fma2(ull a, ull b, ull c) {
    ull d; asm("fma.rn.f32x2 %0, %1, %2, %3;" : "=l"(d) : "l"(a), "l"(b), "l"(c)); return d;
}

// ---------------- K0: zero small accumulators ----------------
__global__ void zero_small() {
    int i = blockIdx.x * blockDim.x + threadIdx.x;
    if (i < B * HEADS * HC * HC) g_G[i] = 0.f;
    if (i < B * C) { g_qn[i] = 0.f; g_kn[i] = 0.f; }
}

// ---------------- shared GEMM core: Y[96 rows x 128 px] = A[96x96] @ X + bias ----------------
// block 16x16, thread tile 6 rows x 8 cols (4 f32x2 pairs), K=96 in two 48-chunks.
__device__ __forceinline__ void gemm_core(
    const float* __restrict__ Ab,   // per-batch A base, row-major [M][96]
    const float* __restrict__ bias, // indexed by global row
    const float* __restrict__ Xb,   // per-batch X base, channel stride HWPIX
    float* __restrict__ Yb)         // per-batch Y base, row stride HWPIX
{
    __shared__ float As[96][49];    // 48-chunk + pad (odd stride: conflict-free)
    __shared__ __align__(16) float Xs[48][128];

    const int m0 = blockIdx.y * 96;
    const long n0 = (long)blockIdx.x * 128;
    const int tx = threadIdx.x, ty = threadIdx.y;
    const int tid = ty * 16 + tx;

    ull acc[6][4];
#pragma unroll
    for (int i = 0; i < 6; i++)
#pragma unroll
        for (int j = 0; j < 4; j++) acc[i][j] = pk2(0.f);

    for (int kc = 0; kc < 96; kc += 48) {
        // load A chunk: 96 x 48 = 4608 = 18 * 256
#pragma unroll
        for (int e = 0; e < 18; e++) {
            int idx = e * 256 + tid;
            int r = idx / 48, kk = idx % 48;
            As[r][kk] = Ab[(long)(m0 + r) * 96 + kc + kk];
        }
        // load X chunk: 48 x 128 floats = 1536 float4 = 6 * 256
#pragma unroll
        for (int e = 0; e < 6; e++) {
            int i4 = e * 256 + tid;
            int kk = i4 >> 5, j = (i4 & 31) * 4;
            *(float4*)&Xs[kk][j] = *(const float4*)&Xb[(long)(kc + kk) * HWPIX + n0 + j];
        }
        __syncthreads();
#pragma unroll
        for (int kk = 0; kk < 48; kk++) {
            ull a2[6];
#pragma unroll
            for (int i = 0; i < 6; i++) a2[i] = pk2(As[ty * 6 + i][kk]);
            const ull* xp = (const ull*)&Xs[kk][tx * 8];
            ull x2[4] = { xp[0], xp[1], xp[2], xp[3] };
#pragma unroll
            for (int i = 0; i < 6; i++)
#pragma unroll
                for (int j = 0; j < 4; j++) acc[i][j] = fma2(a2[i], x2[j], acc[i][j]);
        }
        __syncthreads();
    }
    // epilogue
#pragma unroll
    for (int i = 0; i < 6; i++) {
        int row = m0 + ty * 6 + i;
        float bv = bias[row];
        float2 p0 = unpk2(acc[i][0]), p1 = unpk2(acc[i][1]);
        float2 p2 = unpk2(acc[i][2]), p3 = unpk2(acc[i][3]);
        float* yp = Yb + (long)row * HWPIX + n0 + tx * 8;
        float4 v0 = { p0.x + bv, p0.y + bv, p1.x + bv, p1.y + bv };
        float4 v1 = { p2.x + bv, p2.y + bv, p3.x + bv, p3.y + bv };
        *(float4*)yp = v0;
        *(float4*)(yp + 4) = v1;
    }
}

// K1: qkv = qkv_w @ x + qkv_b   grid (512, 3, 4)
__global__ __launch_bounds__(256) void gemm_qkv(
    const float* __restrict__ qkv_w, const float* __restrict__ qkv_b,
    const float* __restrict__ x)
{
    int b = blockIdx.z;
    gemm_core(qkv_w, qkv_b,
              x + (long)b * C * HWPIX,
              g_qkv + (long)b * C3 * HWPIX);
}

// K4: out = M[b] @ v + proj_b   grid (512, 1, 4)
__global__ __launch_bounds__(256) void gemm_out(
    const float* __restrict__ proj_b, float* __restrict__ out)
{
    int b = blockIdx.z;
    gemm_core(g_M + (long)b * C * C, proj_b,
              g_dw + ((long)b * C3 + 192) * HWPIX,   // v channels
              out + (long)b * C * HWPIX);
}

// ---------------- K2: 3x3 depthwise conv (pad SAME) + q/k sum-of-squares ----------------
// grid (32 bands, 288 ch, 4 b), block 256 (one thread per column), 8 rows per band.
__global__ __launch_bounds__(256) void dwconv(
    const float* __restrict__ dw_w, const float* __restrict__ dw_b)
{
    const int col  = threadIdx.x;
    const int band = blockIdx.x;
    const int ch   = blockIdx.y;
    const int b    = blockIdx.z;
    const float* P = g_qkv + ((long)(b * C3 + ch)) * HWPIX;
    float*       O = g_dw  + ((long)(b * C3 + ch)) * HWPIX;

    float w[9];
#pragma unroll
    for (int t = 0; t < 9; t++) w[t] = __ldg(&dw_w[ch * 9 + t]);
    const float bias = __ldg(&dw_b[ch]);

    const int y0 = band * 8;
    float am1, a0, ap1, bm1, b0c, bp1;

    auto loadrow = [&](int y, float& l, float& m, float& r) {
        if (y < 0 || y > 255) { l = m = r = 0.f; }
        else {
            const float* row = P + y * WW;
            m = row[col];
            l = (col > 0)   ? row[col - 1] : 0.f;
            r = (col < 255) ? row[col + 1] : 0.f;
        }
    };
    loadrow(y0 - 1, am1, a0, ap1);
    loadrow(y0,     bm1, b0c, bp1);

    float ss = 0.f;
#pragma unroll
    for (int dy = 0; dy < 8; dy++) {
        float cm1, c0, cp1;
        loadrow(y0 + dy + 1, cm1, c0, cp1);
        float v = bias
            + w[0] * am1 + w[1] * a0  + w[2] * ap1
            + w[3] * bm1 + w[4] * b0c + w[5] * bp1
            + w[6] * cm1 + w[7] * c0  + w[8] * cp1;
        O[(y0 + dy) * WW + col] = v;
        if (ch < 192) ss += v * v;
        am1 = bm1; a0 = b0c; ap1 = bp1;
        bm1 = cm1; b0c = c0; bp1 = cp1;
    }

    if (ch < 192) {
#pragma unroll
        for (int o = 16; o; o >>= 1) ss += __shfl_down_sync(0xffffffffu, ss, o);
        __shared__ float red[8];
        if ((threadIdx.x & 31) == 0) red[threadIdx.x >> 5] = ss;
        __syncthreads();
        if (threadIdx.x == 0) {
            float t = 0.f;
#pragma unroll
            for (int i = 0; i < 8; i++) t += red[i];
            float* dst = (ch < 96) ? &g_qn[b * C + ch] : &g_kn[b * C + ch - 96];
            atomicAdd(dst, t);
        }
    }
}

// ---------------- K3: Gram G[b,h] += q_head @ k_head^T over pixel chunks ----------------
// grid (32 chunks, 3 heads, 4 b), block 256. chunk = 2048 px = 16 slices of 128.
__global__ __launch_bounds__(256) void gram()
{
    __shared__ float q_s[32 * 132];
    __shared__ __align__(16) float k_s[128 * 36];

    const int chunk = blockIdx.x, h = blockIdx.y, b = blockIdx.z;
    const float* q = g_dw + ((long)(b * C3 + h * HC)) * HWPIX;
    const float* k = g_dw + ((long)(b * C3 + 96 + h * HC)) * HWPIX;
    const int tid = threadIdx.x;
    const int c  = tid >> 3;
    const int d0 = (tid & 7) * 4;

    float acc0 = 0.f, acc1 = 0.f, acc2 = 0.f, acc3 = 0.f;
    const long base = (long)chunk * 2048;

    for (int s = 0; s < 16; s++) {
        const long n = base + s * 128;
        __syncthreads();
#pragma unroll
        for (int e = 0; e < 16; e++) {
            int idx = e * 256 + tid;
            int cc = idx >> 7, p = idx & 127;
            q_s[cc * 132 + p] = q[(long)cc * HWPIX + n + p];
            k_s[p * 36 + cc]  = k[(long)cc * HWPIX + n + p];
        }
        __syncthreads();
#pragma unroll 8
        for (int p = 0; p < 128; p++) {
            float qv = q_s[c * 132 + p];
            float4 kv = *(const float4*)&k_s[p * 36 + d0];
            acc0 += qv * kv.x; acc1 += qv * kv.y;
            acc2 += qv * kv.z; acc3 += qv * kv.w;
        }
    }
    float* Gp = g_G + ((long)((b * HEADS + h) * HC + c)) * HC + d0;
    atomicAdd(Gp + 0, acc0);
    atomicAdd(Gp + 1, acc1);
    atomicAdd(Gp + 2, acc2);
    atomicAdd(Gp + 3, acc3);
}

// ---------------- K3b: attn = softmax(G / (||q|| ||k||)) -> d_out tail ----------------
// grid 12 (b*3+h), block 32 (thread = row c)
__global__ void attn_softmax(float* __restrict__ out)
{
    const int blk = blockIdx.x;
    const int b = blk / 3, h = blk % 3;
    const int c = threadIdx.x;
    float nq = fmaxf(sqrtf(g_qn[b * C + h * HC + c]), 1e-12f);

    float v[32];
#pragma unroll
    for (int d = 0; d < 32; d++) {
        float nk = fmaxf(sqrtf(g_kn[b * C + h * HC + d]), 1e-12f);
        v[d] = g_G[(blk * HC + c) * HC + d] / (nq * nk);
    }
    float m = -1e30f;
#pragma unroll
    for (int d = 0; d < 32; d++) m = fmaxf(m, v[d]);
    float s = 0.f;
#pragma unroll
    for (int d = 0; d < 32; d++) { v[d] = expf(v[d] - m); s += v[d]; }
    float inv = 1.f / s;
    float* ap = out + OUT_ELEMS + (long)blk * (HC * HC) + c * HC;
#pragma unroll
    for (int d = 0; d < 32; d++) ap[d] = v[d] * inv;
}

// ---------------- K3c: M[b] = proj_w @ blockdiag(attn[b]) ----------------
// grid 4, block 256 (36 entries each)
__global__ void make_M(const float* __restrict__ proj_w, const float* __restrict__ out)
{
    const int b = blockIdx.x, tid = threadIdx.x;
    const float* attn = out + OUT_ELEMS;
#pragma unroll 4
    for (int e = 0; e < 36; e++) {
        int idx = e * 256 + tid;        // 0..9215
        int o = idx / 96, g = idx % 96;
        int h = g >> 5, d = g & 31;
        const float* arow = attn + (long)(b * HEADS + h) * (HC * HC) + d; // [c][d] stride 32
        const float* prow = proj_w + o * 96 + h * HC;
        float s = 0.f;
#pragma unroll
        for (int cc = 0; cc < 32; cc++) s += prow[cc] * arow[cc * 32];
        g_M[(long)b * C * C + idx] = s;
    }
}

// ---------------- launch ----------------
extern "C" void kernel_launch(void* const* d_in, const int* in_sizes, int n_in,
                              void* d_out, int out_size)
{
    const float* x      = (const float*)d_in[0];
    const float* qkv_w  = (const float*)d_in[1];
    const float* qkv_b  = (const float*)d_in[2];
    const float* dw_w   = (const float*)d_in[3];
    const float* dw_b   = (const float*)d_in[4];
    const float* proj_w = (const float*)d_in[5];
    const float* proj_b = (const float*)d_in[6];
    float* out = (float*)d_out;

    zero_small<<<48, 256>>>();
    gemm_qkv<<<dim3(512, 3, B), dim3(16, 16)>>>(qkv_w, qkv_b, x);
    dwconv<<<dim3(32, C3, B), 256>>>(dw_w, dw_b);
    gram<<<dim3(32, HEADS, B), 256>>>();
    attn_softmax<<<12, 32>>>(out);
    make_M<<<B, 256>>>(proj_w, out);
    gemm_out<<<dim3(512, 1, B), dim3(16, 16)>>>(proj_b, out);
}